// round 4
// baseline (speedup 1.0000x reference)
#include <cuda_runtime.h>
#include <math.h>

#define Bdim   128
#define TU     256
#define TB     128
#define TP     64
#define Hd     512
#define Ed     512
#define Vd     3000
#define VOOVd  3400
#define PTRd   32
#define XDIM   2080          // E + 3H + PTR
#define G3H    1536
#define CPSW   3128          // V + TB
#define NEGV   (-1e20f)

__device__ float g_pre1 [Bdim * Hd];
__device__ float g_score[Bdim * (TU + TB + TP)];
__device__ float g_X    [Bdim * XDIM];
__device__ float g_gi   [Bdim * G3H];
__device__ float g_gh   [Bdim * G3H];
__device__ float g_hnew [Bdim * Hd];
__device__ float g_gen  [Bdim * Vd];
__device__ float g_cpraw[Bdim * TB];
__device__ float g_cps  [Bdim * CPSW];

__device__ __forceinline__ unsigned long long pack2(float x, float y) {
    unsigned long long r;
    asm("mov.b64 %0, {%1, %2};" : "=l"(r) : "f"(x), "f"(y));
    return r;
}
__device__ __forceinline__ void unpack2(unsigned long long p, float& x, float& y) {
    asm("mov.b64 {%0, %1}, %2;" : "=f"(x), "=f"(y) : "l"(p));
}
__device__ __forceinline__ unsigned long long ffma2(unsigned long long a,
                                                    unsigned long long b,
                                                    unsigned long long c) {
    unsigned long long d;
    asm("fma.rn.f32x2 %0, %1, %2, %3;" : "=l"(d) : "l"(a), "l"(b), "l"(c));
    return d;
}

// C = A[MxK] @ W[NxK]^T, tiles 128x64x16, 8x8 microtile, f32x2 FMA.
// MODE 0: C[r*ldc+c] = acc + bias[c]
// MODE 1: C[r] += sum_c tanh(acc + bias[(r/Tdim)*H + c]) * v[c]   (attention score)
// MODE 2: C[r] += sum_c tanh(acc + bias[c]) * v[(r/Tdim)*H + c]   (copy raw)
template<int MODE>
__global__ void __launch_bounds__(128)
gemm_k(const float* __restrict__ A, int lda,
       const float* __restrict__ W, int ldw,
       const float* __restrict__ bias,
       const float* __restrict__ v,
       float* __restrict__ C, int ldc,
       int M, int N, int K, int Tdim)
{
    __shared__ float As[16][128];
    __shared__ float Bs[16][64];
    const int tid  = threadIdx.x;
    const int row0 = blockIdx.x * 128;
    const int col0 = blockIdx.y * 64;

    const int  a_row = row0 + tid;
    const bool a_ok  = a_row < M;
    const float* Ap  = A + (size_t)(a_ok ? a_row : 0) * lda;

    const int  b_hl = tid >> 1;
    const int  b_h  = col0 + b_hl;
    const int  b_k  = (tid & 1) << 3;
    const bool b_ok = b_h < N;
    const float* Wp  = W + (size_t)(b_ok ? b_h : 0) * ldw + b_k;

    unsigned long long acc2[8][4];
#pragma unroll
    for (int i = 0; i < 8; i++)
#pragma unroll
        for (int j = 0; j < 4; j++) acc2[i][j] = 0ull;

    const int rg = tid >> 3;
    const int cg = tid & 7;

    for (int kt = 0; kt < K; kt += 16) {
        float4 av0, av1, av2, av3, bv0, bv1;
        if (a_ok) {
            av0 = *(const float4*)(Ap + kt);      av1 = *(const float4*)(Ap + kt + 4);
            av2 = *(const float4*)(Ap + kt + 8);  av3 = *(const float4*)(Ap + kt + 12);
        } else av0 = av1 = av2 = av3 = make_float4(0.f,0.f,0.f,0.f);
        if (b_ok) {
            bv0 = *(const float4*)(Wp + kt);      bv1 = *(const float4*)(Wp + kt + 4);
        } else bv0 = bv1 = make_float4(0.f,0.f,0.f,0.f);
        __syncthreads();
        As[0][tid]=av0.x;  As[1][tid]=av0.y;  As[2][tid]=av0.z;  As[3][tid]=av0.w;
        As[4][tid]=av1.x;  As[5][tid]=av1.y;  As[6][tid]=av1.z;  As[7][tid]=av1.w;
        As[8][tid]=av2.x;  As[9][tid]=av2.y;  As[10][tid]=av2.z; As[11][tid]=av2.w;
        As[12][tid]=av3.x; As[13][tid]=av3.y; As[14][tid]=av3.z; As[15][tid]=av3.w;
        Bs[b_k+0][b_hl]=bv0.x; Bs[b_k+1][b_hl]=bv0.y; Bs[b_k+2][b_hl]=bv0.z; Bs[b_k+3][b_hl]=bv0.w;
        Bs[b_k+4][b_hl]=bv1.x; Bs[b_k+5][b_hl]=bv1.y; Bs[b_k+6][b_hl]=bv1.z; Bs[b_k+7][b_hl]=bv1.w;
        __syncthreads();
#pragma unroll
        for (int kk = 0; kk < 16; kk++) {
            float4 af0 = *(const float4*)&As[kk][rg*8];
            float4 af1 = *(const float4*)&As[kk][rg*8+4];
            float4 bf0 = *(const float4*)&Bs[kk][cg*8];
            float4 bf1 = *(const float4*)&Bs[kk][cg*8+4];
            unsigned long long a2[8], b2[4];
            a2[0]=pack2(af0.x,af0.x); a2[1]=pack2(af0.y,af0.y);
            a2[2]=pack2(af0.z,af0.z); a2[3]=pack2(af0.w,af0.w);
            a2[4]=pack2(af1.x,af1.x); a2[5]=pack2(af1.y,af1.y);
            a2[6]=pack2(af1.z,af1.z); a2[7]=pack2(af1.w,af1.w);
            b2[0]=pack2(bf0.x,bf0.y); b2[1]=pack2(bf0.z,bf0.w);
            b2[2]=pack2(bf1.x,bf1.y); b2[3]=pack2(bf1.z,bf1.w);
#pragma unroll
            for (int i = 0; i < 8; i++)
#pragma unroll
                for (int j = 0; j < 4; j++)
                    acc2[i][j] = ffma2(a2[i], b2[j], acc2[i][j]);
        }
    }

    float acc[8][8];
#pragma unroll
    for (int i = 0; i < 8; i++)
#pragma unroll
        for (int j = 0; j < 4; j++)
            unpack2(acc2[i][j], acc[i][2*j], acc[i][2*j+1]);

    if (MODE == 0) {
#pragma unroll
        for (int i = 0; i < 8; i++) {
            int r = row0 + rg*8 + i;
            if (r >= M) continue;
#pragma unroll
            for (int j = 0; j < 8; j++) {
                int c = col0 + cg*8 + j;
                if (c < N) C[(size_t)r*ldc + c] = acc[i][j] + bias[c];
            }
        }
    } else {
#pragma unroll
        for (int i = 0; i < 8; i++) {
            int r = row0 + rg*8 + i;
            float s = 0.f;
            if (r < M) {
                int bb = r / Tdim;
#pragma unroll
                for (int j = 0; j < 8; j++) {
                    int c = col0 + cg*8 + j;
                    if (c < N) {
                        if (MODE == 1) s += tanhf(acc[i][j] + bias[bb*Hd + c]) * v[c];
                        else           s += tanhf(acc[i][j] + bias[c]) * v[bb*Hd + c];
                    }
                }
            }
            s += __shfl_down_sync(0xffffffffu, s, 4, 8);
            s += __shfl_down_sync(0xffffffffu, s, 2, 8);
            s += __shfl_down_sync(0xffffffffu, s, 1, 8);
            if (cg == 0 && r < M) atomicAdd(&C[r], s);
        }
    }
}

__device__ __forceinline__ float block_reduce_max(float val, float* red) {
    int tid = threadIdx.x, nw = blockDim.x >> 5;
    for (int o = 16; o; o >>= 1) val = fmaxf(val, __shfl_down_sync(0xffffffffu, val, o));
    if ((tid & 31) == 0) red[tid >> 5] = val;
    __syncthreads();
    if (tid < 32) {
        val = (tid < nw) ? red[tid] : -3.0e38f;
        for (int o = 16; o; o >>= 1) val = fmaxf(val, __shfl_down_sync(0xffffffffu, val, o));
        if (tid == 0) red[0] = val;
    }
    __syncthreads();
    val = red[0];
    __syncthreads();
    return val;
}
__device__ __forceinline__ float block_reduce_sum(float val, float* red) {
    int tid = threadIdx.x, nw = blockDim.x >> 5;
    for (int o = 16; o; o >>= 1) val += __shfl_down_sync(0xffffffffu, val, o);
    if ((tid & 31) == 0) red[tid >> 5] = val;
    __syncthreads();
    if (tid < 32) {
        val = (tid < nw) ? red[tid] : 0.f;
        for (int o = 16; o; o >>= 1) val += __shfl_down_sync(0xffffffffu, val, o);
        if (tid == 0) red[0] = val;
    }
    __syncthreads();
    val = red[0];
    __syncthreads();
    return val;
}

// masked softmax over T + weighted context sum, written into X slice
__global__ void __launch_bounds__(256)
softmax_ctx_k(const float* __restrict__ score, const int* __restrict__ ids,
              const float* __restrict__ enc, int T,
              float* __restrict__ xout, int xofs)
{
    const int b = blockIdx.x, tid = threadIdx.x;
    __shared__ float aw[TU];
    __shared__ float red[32];
    float sv = -3.0e38f;
    if (tid < T) {
        float s = score[b*T + tid];
        if (ids[b*T + tid] == 0) s = NEGV;
        aw[tid] = s; sv = s;
    }
    float m = block_reduce_max(sv, red);
    float e = 0.f;
    if (tid < T) { e = expf(aw[tid] - m); aw[tid] = e; }
    float ssum = block_reduce_sum(e, red);
    float inv = 1.f / ssum;
    float c0 = 0.f, c1 = 0.f;
    const float* eb = enc + (size_t)b * T * Hd;
#pragma unroll 4
    for (int t = 0; t < T; t++) {
        float w = aw[t] * inv;
        c0 = fmaf(w, eb[t*Hd + tid],       c0);
        c1 = fmaf(w, eb[t*Hd + 256 + tid], c1);
    }
    float* xp = xout + (size_t)b * XDIM + xofs;
    xp[tid] = c0; xp[256 + tid] = c1;
}

__global__ void embdb_k(const int* __restrict__ w, const float* __restrict__ emb,
                        const float* __restrict__ db, float* __restrict__ X)
{
    int b = blockIdx.x, tid = threadIdx.x;
    int widx = w[b];
    for (int i = tid; i < Ed; i += 256)
        X[(size_t)b*XDIM + i] = emb[(size_t)widx*Ed + i];
    if (tid < PTRd)
        X[(size_t)b*XDIM + Ed + 3*Hd + tid] = db[b*PTRd + tid];
}

__global__ void gate_k(const float* __restrict__ gi, const float* __restrict__ gh,
                       const float* __restrict__ h0, float* __restrict__ hnew)
{
    int b = blockIdx.x, h = threadIdx.x;
    float ir  = gi[b*G3H + h],        hr = gh[b*G3H + h];
    float iz  = gi[b*G3H + Hd + h],   hz = gh[b*G3H + Hd + h];
    float inn = gi[b*G3H + 2*Hd + h], hn = gh[b*G3H + 2*Hd + h];
    float r = 1.f / (1.f + expf(-(ir + hr)));
    float z = 1.f / (1.f + expf(-(iz + hz)));
    float n = tanhf(inn + r * hn);
    hnew[b*Hd + h] = (1.f - z) * n + z * h0[b*Hd + h];
}

// cps[b, col] += masked cp_raw[b,t]   (replaces einsum with one-hot)
__global__ void scatter_k(const float* __restrict__ cpraw, const int* __restrict__ bids,
                          const int* __restrict__ nounk, float* __restrict__ cps)
{
    int b = blockIdx.x, t = threadIdx.x;
    float val = cpraw[b*TB + t];
    if (bids[b*TB + t] == 0) val = NEGV;
    int nk = nounk[b*TB + t];
    int col = (nk < Vd) ? nk : (Vd + t);
    atomicAdd(&cps[(size_t)b*CPSW + col], val);
}

__global__ void __launch_bounds__(512)
final_k(const float* __restrict__ gen, const float* __restrict__ cps,
        const int* __restrict__ nounk, float* __restrict__ out)
{
    const int b = blockIdx.x, tid = threadIdx.x;
    const float* gb = gen + (size_t)b * Vd;
    const float* cb = cps + (size_t)b * CPSW;
    __shared__ float red[32];
    __shared__ float adds[VOOVd - Vd];

    float m = -3.0e38f;
    for (int i = tid; i < Vd;   i += 512) m = fmaxf(m, gb[i]);
    for (int i = tid; i < CPSW; i += 512) m = fmaxf(m, cb[i]);
    m = block_reduce_max(m, red);

    float s = 0.f;
    for (int i = tid; i < Vd;   i += 512) s += expf(gb[i] - m);
    for (int i = tid; i < CPSW; i += 512) s += expf(cb[i] - m);
    s = block_reduce_sum(s, red);
    float logS = logf(s);

    for (int i = tid; i < Vd; i += 512)
        out[(size_t)b*VOOVd + i] = logf(expf(gb[i] - m) + expf(cb[i] - m)) - logS;

    for (int i = tid; i < (VOOVd - Vd); i += 512) adds[i] = 0.f;
    __syncthreads();
    if (tid < TB) {
        int nk = nounk[b*TB + tid];
        if (nk >= Vd) atomicAdd(&adds[nk - Vd], expf(cb[Vd + tid] - m) / s);
    }
    __syncthreads();
    for (int i = tid; i < (VOOVd - Vd); i += 512) {
        float a = adds[i];
        out[(size_t)b*VOOVd + Vd + i] = (a > 0.f) ? logf(fmaxf(a, 1e-38f)) : NEGV;
    }
}

extern "C" void kernel_launch(void* const* d_in, const int* in_sizes, int n_in,
                              void* d_out, int out_size)
{
    (void)in_sizes; (void)n_in; (void)out_size;
    const int*   dec_last_w = (const int*)  d_in[0];
    const float* dec_last_h = (const float*)d_in[1];
    const float* usdx_h     = (const float*)d_in[2];
    const float* bspn_h     = (const float*)d_in[3];
    const float* pvaspn_h   = (const float*)d_in[4];
    const float* db         = (const float*)d_in[5];
    const int*   usdx_ids   = (const int*)  d_in[6];
    const int*   bspn_ids   = (const int*)  d_in[7];
    const int*   pvaspn_ids = (const int*)  d_in[8];
    const int*   bspn_nounk = (const int*)  d_in[9];
    /* d_in[10] = bspn_onehot — unused, replaced by scatter */
    const float* emb_table  = (const float*)d_in[11];
    const float* attn_W     = (const float*)d_in[12];
    const float* attn_b     = (const float*)d_in[13];
    const float* v_w        = (const float*)d_in[14];
    const float* Wcopy_w    = (const float*)d_in[15];
    const float* Wcopy_b    = (const float*)d_in[16];
    const float* Wgen_w     = (const float*)d_in[17];
    const float* Wgen_b     = (const float*)d_in[18];
    const float* W_ih       = (const float*)d_in[19];
    const float* W_hh       = (const float*)d_in[20];
    const float* b_ih       = (const float*)d_in[21];
    const float* b_hh       = (const float*)d_in[22];
    float* out = (float*)d_out;

    float *pre1,*score,*X,*gi,*gh,*hnew,*gen,*cpraw,*cps;
    cudaGetSymbolAddress((void**)&pre1,  g_pre1);
    cudaGetSymbolAddress((void**)&score, g_score);
    cudaGetSymbolAddress((void**)&X,     g_X);
    cudaGetSymbolAddress((void**)&gi,    g_gi);
    cudaGetSymbolAddress((void**)&gh,    g_gh);
    cudaGetSymbolAddress((void**)&hnew,  g_hnew);
    cudaGetSymbolAddress((void**)&gen,   g_gen);
    cudaGetSymbolAddress((void**)&cpraw, g_cpraw);
    cudaGetSymbolAddress((void**)&cps,   g_cps);

    cudaMemsetAsync(score, 0, sizeof(float)*Bdim*(TU+TB+TP));
    cudaMemsetAsync(cpraw, 0, sizeof(float)*Bdim*TB);
    cudaMemsetAsync(cps,   0, sizeof(float)*(size_t)Bdim*CPSW);

    dim3 blk(128);

    // pre1 = h0 @ W1^T + attn_b   (W1 = attn_W[:, :H])
    gemm_k<0><<<dim3(1, Hd/64), blk>>>(dec_last_h, Hd, attn_W, 2*Hd, attn_b,
                                       nullptr, pre1, Hd, Bdim, Hd, Hd, 1);

    // attention scores with fused tanh·v epilogue (W2 = attn_W[:, H:])
    gemm_k<1><<<dim3(Bdim*TU/128, Hd/64), blk>>>(usdx_h, Hd, attn_W + Hd, 2*Hd,
        pre1, v_w, score, 0, Bdim*TU, Hd, Hd, TU);
    gemm_k<1><<<dim3(Bdim*TB/128, Hd/64), blk>>>(bspn_h, Hd, attn_W + Hd, 2*Hd,
        pre1, v_w, score + Bdim*TU, 0, Bdim*TB, Hd, Hd, TB);
    gemm_k<1><<<dim3(Bdim*TP/128, Hd/64), blk>>>(pvaspn_h, Hd, attn_W + Hd, 2*Hd,
        pre1, v_w, score + Bdim*(TU+TB), 0, Bdim*TP, Hd, Hd, TP);

    softmax_ctx_k<<<Bdim, 256>>>(score,                   usdx_ids,   usdx_h,   TU, X, Ed);
    softmax_ctx_k<<<Bdim, 256>>>(score + Bdim*TU,         bspn_ids,   bspn_h,   TB, X, Ed + Hd);
    softmax_ctx_k<<<Bdim, 256>>>(score + Bdim*(TU+TB),    pvaspn_ids, pvaspn_h, TP, X, Ed + 2*Hd);
    embdb_k<<<Bdim, 256>>>(dec_last_w, emb_table, db, X);

    // GRU
    gemm_k<0><<<dim3(1, G3H/64), blk>>>(X, XDIM, W_ih, XDIM, b_ih,
                                        nullptr, gi, G3H, Bdim, G3H, XDIM, 1);
    gemm_k<0><<<dim3(1, G3H/64), blk>>>(dec_last_h, Hd, W_hh, Hd, b_hh,
                                        nullptr, gh, G3H, Bdim, G3H, Hd, 1);
    gate_k<<<Bdim, Hd>>>(gi, gh, dec_last_h, hnew);

    // gen = hnew @ Wgen^T + b
    gemm_k<0><<<dim3(1, (Vd + 63)/64), blk>>>(hnew, Hd, Wgen_w, Hd, Wgen_b,
                                              nullptr, gen, Vd, Bdim, Vd, Hd, 1);

    // cp_raw[b,t] = sum_h tanh(bspn_h@Wcopy^T + b)[b,t,h] * hnew[b,h]
    gemm_k<2><<<dim3(Bdim*TB/128, Hd/64), blk>>>(bspn_h, Hd, Wcopy_w, Hd, Wcopy_b,
        hnew, cpraw, 0, Bdim*TB, Hd, Hd, TB);

    scatter_k<<<Bdim, TB>>>(cpraw, bspn_ids, bspn_nounk, cps);
    final_k<<<Bdim, 512>>>(gen, cps, bspn_nounk, out);
}

// round 7
// speedup vs baseline: 1.7428x; 1.7428x over previous
#include <cuda_runtime.h>
#include <cuda_bf16.h>
#include <math.h>
#include <stdint.h>

#define Bdim   128
#define TU     256
#define TB     128
#define TP     64
#define Hd     512
#define Vd     3000
#define VOOVd  3400
#define PTRd   32
#define XP     2112      // padded X width (2080 -> 33*64)
#define XR     2080
#define G3H    1536
#define CPSW   3128
#define NEGV   (-1e20f)

// ---------------- scratch ----------------
__device__ float g_pre1 [Bdim*Hd];
__device__ float g_score[Bdim*(TU+TB+TP)];
__device__ __nv_bfloat16 g_Xbf[Bdim*XP];
__device__ float g_gi   [Bdim*G3H];
__device__ float g_gh   [Bdim*G3H];
__device__ float g_hnew [Bdim*Hd];
__device__ __nv_bfloat16 g_hnewbf[Bdim*Hd];
__device__ float g_gen  [Bdim*Vd];
__device__ float g_cpraw[Bdim*TB];
__device__ float g_cps  [Bdim*CPSW];
__device__ __nv_bfloat16 g_Wa [Hd*Hd];
__device__ __nv_bfloat16 g_Wb [Hd*Hd];
__device__ __nv_bfloat16 g_Wc [Hd*Hd];
__device__ __nv_bfloat16 g_Whh[G3H*Hd];
__device__ __nv_bfloat16 g_Wih[G3H*XP];
__device__ __nv_bfloat16 g_Wgn[Vd*Hd];

// ---------------- helpers ----------------
__device__ __forceinline__ uint32_t smem_u32(const void* p) {
    uint32_t a;
    asm("{ .reg .u64 t; cvta.to.shared.u64 t, %1; cvt.u32.u64 %0, t; }" : "=r"(a) : "l"(p));
    return a;
}
__device__ __forceinline__ void ldmx4(uint32_t* r, uint32_t addr) {
    asm volatile("ldmatrix.sync.aligned.m8n8.x4.shared.b16 {%0,%1,%2,%3}, [%4];"
        : "=r"(r[0]), "=r"(r[1]), "=r"(r[2]), "=r"(r[3]) : "r"(addr));
}
__device__ __forceinline__ void mma16816(float* d, const uint32_t* a, const uint32_t* b) {
    asm volatile("mma.sync.aligned.m16n8k16.row.col.f32.bf16.bf16.f32 "
        "{%0,%1,%2,%3}, {%4,%5,%6,%7}, {%8,%9}, {%0,%1,%2,%3};"
        : "+f"(d[0]), "+f"(d[1]), "+f"(d[2]), "+f"(d[3])
        : "r"(a[0]), "r"(a[1]), "r"(a[2]), "r"(a[3]), "r"(b[0]), "r"(b[1]));
}
#define SWZ(x) ((x) ^ (((x) >> 3) & 0x70))

__device__ __forceinline__ float tanh_f(float x) {
    float a = fabsf(x);
    if (a < 0.6f) {
        float t = x * x;
        return x * (1.f + t * (-0.33333334f + t * (0.13333333f +
                    t * (-0.05396825f + t * 0.02186949f))));
    }
    return tanhf(x);   // rare (inputs have sigma ~0.06)
}

// ==================== mma.sync bf16 GEMM ====================
// C = A[M x K] @ B[Nb x K]^T, fp32 accumulate.
// MODE 0: C[r, n] = acc + add[n]                (grid.y tiles N by 128)
// MODE 1: C[r]   = sum_n tanh(acc + add[bi,n]) * mul[bi,n]   (N = 512, grid.y = 1)
// ADT: 0 = A is f32 (convert on the STS path), 1 = A is bf16
template<int MODE, int ADT>
__global__ void __launch_bounds__(256, 2)
mma_gemm(const void* __restrict__ Ap, int lda, int KC /*K/64*/,
         const __nv_bfloat16* __restrict__ Bp, int ldb, int Nb,
         const float* __restrict__ addp, int add_per_b,
         const float* __restrict__ mulp, int mul_per_b,
         int Tdim, float* __restrict__ Co, int ldc)
{
    __shared__ __align__(128) char As_s[16384];   // 128 rows x 64 bf16 (SW128)
    __shared__ __align__(128) char Bs_s[16384];   // 128 rows x 64 bf16 (SW128)
    __shared__ float add_s[1024];
    __shared__ float mul_s[1024];
    __shared__ float rowacc[128];

    const int tid   = threadIdx.x;
    const int wid   = tid >> 5, lane = tid & 31;
    const int warpM = wid & 3, warpN = wid >> 2;
    const int row0  = blockIdx.x * 128;
    const uint32_t As_b = smem_u32(As_s);
    const uint32_t Bs_b = smem_u32(Bs_s);

    if (MODE == 0) {
        int col0 = blockIdx.y * 128;
        if (tid < 128) add_s[tid] = (col0 + tid < Nb) ? addp[col0 + tid] : 0.f;
    } else {
        int b0 = row0 / Tdim;
        for (int i = tid; i < 1024; i += 256) {
            int bi = i >> 9, n = i & 511;
            int b = b0 + bi; if (b > Bdim - 1) b = Bdim - 1;
            add_s[i] = addp[add_per_b ? (b * Hd + n) : n];
            mul_s[i] = mulp[mul_per_b ? (b * Hd + n) : n];
        }
        if (tid < 128) rowacc[tid] = 0.f;
    }

    float rs[4] = {0.f, 0.f, 0.f, 0.f};
    const int NTER = (MODE == 1) ? 4 : 1;

    for (int nt = 0; nt < NTER; nt++) {
        const int nb0 = (MODE == 1) ? nt * 128 : blockIdx.y * 128;
        float acc[2][8][4];
#pragma unroll
        for (int t = 0; t < 2; t++)
#pragma unroll
            for (int j = 0; j < 8; j++)
#pragma unroll
                for (int q = 0; q < 4; q++) acc[t][j][q] = 0.f;

        for (int kt = 0; kt < KC; kt++) {
            const int k0 = kt * 64;
            __syncthreads();
            // A tile: 128 x 64 bf16
#pragma unroll 4
            for (int u = tid; u < 2048; u += 256) {
                int row = u >> 4, k = (u & 15) << 2;
                uint2 val;
                if (ADT == 0) {
                    const float4 f = *(const float4*)((const float*)Ap +
                                        (size_t)(row0 + row) * lda + k0 + k);
                    __nv_bfloat162 p0 = __floats2bfloat162_rn(f.x, f.y);
                    __nv_bfloat162 p1 = __floats2bfloat162_rn(f.z, f.w);
                    val.x = *(uint32_t*)&p0; val.y = *(uint32_t*)&p1;
                } else {
                    val = *(const uint2*)((const __nv_bfloat16*)Ap +
                                        (size_t)(row0 + row) * lda + k0 + k);
                }
                *(uint2*)(As_s + SWZ(row * 128 + k * 2)) = val;
            }
            // B tile: 128 x 64 bf16 (rows = n, guarded)
#pragma unroll 4
            for (int u = tid; u < 2048; u += 256) {
                int row = u >> 4, k = (u & 15) << 2;
                int n = nb0 + row;
                uint2 val = make_uint2(0u, 0u);
                if (n < Nb) val = *(const uint2*)(Bp + (size_t)n * ldb + k0 + k);
                *(uint2*)(Bs_s + SWZ(row * 128 + k * 2)) = val;
            }
            __syncthreads();
#pragma unroll
            for (int kc = 0; kc < 4; kc++) {
                uint32_t af[2][4];
#pragma unroll
                for (int t = 0; t < 2; t++) {
                    int row  = warpM * 32 + t * 16 + (lane & 15);
                    int bcol = kc * 32 + ((lane >> 4) << 4);
                    ldmx4(af[t], As_b + SWZ(row * 128 + bcol));
                }
                uint32_t bfr[4][4];
#pragma unroll
                for (int g = 0; g < 4; g++) {
                    int row  = warpN * 64 + g * 16 + (lane & 7) + ((lane >> 4) << 3);
                    int bcol = kc * 32 + (((lane >> 3) & 1) << 4);
                    ldmx4(bfr[g], Bs_b + SWZ(row * 128 + bcol));
                }
#pragma unroll
                for (int t = 0; t < 2; t++)
#pragma unroll
                    for (int g = 0; g < 4; g++) {
                        mma16816(acc[t][2*g],   af[t], &bfr[g][0]);
                        mma16816(acc[t][2*g+1], af[t], &bfr[g][2]);
                    }
            }
        }

        if (MODE == 0) {
            const int col0 = nb0;
#pragma unroll
            for (int t = 0; t < 2; t++) {
                int r0 = row0 + warpM * 32 + t * 16 + (lane >> 2);
#pragma unroll
                for (int j = 0; j < 8; j++) {
                    int c = col0 + warpN * 64 + j * 8 + ((lane & 3) << 1);
                    if (c < Nb) {
                        float b0v = add_s[c - col0], b1v = add_s[c + 1 - col0];
                        Co[(size_t)r0 * ldc + c]     = acc[t][j][0] + b0v;
                        Co[(size_t)r0 * ldc + c + 1] = acc[t][j][1] + b1v;
                        Co[(size_t)(r0+8) * ldc + c]     = acc[t][j][2] + b0v;
                        Co[(size_t)(r0+8) * ldc + c + 1] = acc[t][j][3] + b1v;
                    }
                }
            }
        } else {
#pragma unroll
            for (int t = 0; t < 2; t++) {
                int bi = (warpM * 32 + t * 16) / Tdim;
                const float* aS = add_s + bi * 512;
                const float* mS = mul_s + bi * 512;
#pragma unroll
                for (int j = 0; j < 8; j++) {
                    int n = nt * 128 + warpN * 64 + j * 8 + ((lane & 3) << 1);
                    rs[t*2+0] += tanh_f(acc[t][j][0] + aS[n])   * mS[n]
                               + tanh_f(acc[t][j][1] + aS[n+1]) * mS[n+1];
                    rs[t*2+1] += tanh_f(acc[t][j][2] + aS[n])   * mS[n]
                               + tanh_f(acc[t][j][3] + aS[n+1]) * mS[n+1];
                }
            }
        }
    }

    if (MODE == 1) {
#pragma unroll
        for (int q = 0; q < 4; q++) {
            rs[q] += __shfl_xor_sync(0xffffffffu, rs[q], 1);
            rs[q] += __shfl_xor_sync(0xffffffffu, rs[q], 2);
        }
        if ((lane & 3) == 0) {
#pragma unroll
            for (int t = 0; t < 2; t++) {
                int rloc = warpM * 32 + t * 16 + (lane >> 2);
                atomicAdd(&rowacc[rloc],     rs[t*2+0]);
                atomicAdd(&rowacc[rloc + 8], rs[t*2+1]);
            }
        }
        __syncthreads();
        if (tid < 128) Co[row0 + tid] = rowacc[tid];
    }
}

// ---------------- weight f32->bf16 converter (slice/pad) ----------------
__global__ void conv_k(__nv_bfloat16* __restrict__ dst, const float* __restrict__ src,
                       int rows, int cols, int lds, int coff, int ldd)
{
    int n = rows * ldd;
    for (int i = blockIdx.x * blockDim.x + threadIdx.x; i < n; i += gridDim.x * blockDim.x) {
        int r = i / ldd, c = i - r * ldd;
        dst[i] = __float2bfloat16((c < cols) ? src[(size_t)r * lds + coff + c] : 0.f);
    }
}

// ---------------- reductions ----------------
__device__ __forceinline__ float block_reduce_max(float val, float* red) {
    int tid = threadIdx.x, nw = blockDim.x >> 5;
    for (int o = 16; o; o >>= 1) val = fmaxf(val, __shfl_down_sync(0xffffffffu, val, o));
    if ((tid & 31) == 0) red[tid >> 5] = val;
    __syncthreads();
    if (tid < 32) {
        val = (tid < nw) ? red[tid] : -3.0e38f;
        for (int o = 16; o; o >>= 1) val = fmaxf(val, __shfl_down_sync(0xffffffffu, val, o));
        if (tid == 0) red[0] = val;
    }
    __syncthreads();
    val = red[0]; __syncthreads();
    return val;
}
__device__ __forceinline__ float block_reduce_sum(float val, float* red) {
    int tid = threadIdx.x, nw = blockDim.x >> 5;
    for (int o = 16; o; o >>= 1) val += __shfl_down_sync(0xffffffffu, val, o);
    if ((tid & 31) == 0) red[tid >> 5] = val;
    __syncthreads();
    if (tid < 32) {
        val = (tid < nw) ? red[tid] : 0.f;
        for (int o = 16; o; o >>= 1) val += __shfl_down_sync(0xffffffffu, val, o);
        if (tid == 0) red[0] = val;
    }
    __syncthreads();
    val = red[0]; __syncthreads();
    return val;
}

// masked softmax + context, written (bf16) into X slice
__global__ void __launch_bounds__(256)
softmax_ctx_k(const float* __restrict__ score, const int* __restrict__ ids,
              const float* __restrict__ enc, int T,
              __nv_bfloat16* __restrict__ xout, int xofs)
{
    const int b = blockIdx.x, tid = threadIdx.x;
    __shared__ float aw[TU];
    __shared__ float red[32];
    float sv = -3.0e38f;
    if (tid < T) {
        float s = score[b * T + tid];
        if (ids[b * T + tid] == 0) s = NEGV;
        aw[tid] = s; sv = s;
    }
    float m = block_reduce_max(sv, red);
    float e = 0.f;
    if (tid < T) { e = expf(aw[tid] - m); aw[tid] = e; }
    float ssum = block_reduce_sum(e, red);
    float inv = 1.f / ssum;
    float c0 = 0.f, c1 = 0.f;
    const float* eb = enc + (size_t)b * T * Hd;
#pragma unroll 4
    for (int t = 0; t < T; t++) {
        float w = aw[t] * inv;
        c0 = fmaf(w, eb[t * Hd + tid],       c0);
        c1 = fmaf(w, eb[t * Hd + 256 + tid], c1);
    }
    __nv_bfloat16* xp = xout + (size_t)b * XP + xofs;
    xp[tid]       = __float2bfloat16(c0);
    xp[256 + tid] = __float2bfloat16(c1);
}

__global__ void embdb_k(const int* __restrict__ w, const float* __restrict__ emb,
                        const float* __restrict__ db, __nv_bfloat16* __restrict__ X)
{
    int b = blockIdx.x, tid = threadIdx.x;
    int widx = w[b];
    for (int i = tid; i < Hd; i += 256)
        X[(size_t)b * XP + i] = __float2bfloat16(emb[(size_t)widx * Hd + i]);
    if (tid < PTRd)
        X[(size_t)b * XP + 2048 + tid] = __float2bfloat16(db[b * PTRd + tid]);
    if (tid >= PTRd && tid < PTRd + (XP - XR))
        X[(size_t)b * XP + XR + (tid - PTRd)] = __float2bfloat16(0.f);
}

__global__ void gate_k(const float* __restrict__ gi, const float* __restrict__ gh,
                       const float* __restrict__ h0, float* __restrict__ hnew,
                       __nv_bfloat16* __restrict__ hnewbf)
{
    int b = blockIdx.x, h = threadIdx.x;
    float ir  = gi[b*G3H + h],        hr = gh[b*G3H + h];
    float iz  = gi[b*G3H + Hd + h],   hz = gh[b*G3H + Hd + h];
    float inn = gi[b*G3H + 2*Hd + h], hn = gh[b*G3H + 2*Hd + h];
    float rr = 1.f / (1.f + expf(-(ir + hr)));
    float z  = 1.f / (1.f + expf(-(iz + hz)));
    float n  = tanhf(inn + rr * hn);
    float v  = (1.f - z) * n + z * h0[b*Hd + h];
    hnew[b*Hd + h]   = v;
    hnewbf[b*Hd + h] = __float2bfloat16(v);
}

__global__ void scatter_k(const float* __restrict__ cpraw, const int* __restrict__ bids,
                          const int* __restrict__ nounk, float* __restrict__ cps)
{
    int b = blockIdx.x, t = threadIdx.x;
    float val = cpraw[b*TB + t];
    if (bids[b*TB + t] == 0) val = NEGV;
    int nk = nounk[b*TB + t];
    int col = (nk < Vd) ? nk : (Vd + t);
    atomicAdd(&cps[(size_t)b*CPSW + col], val);
}

__global__ void __launch_bounds__(512)
final_k(const float* __restrict__ gen, const float* __restrict__ cps,
        const int* __restrict__ nounk, float* __restrict__ out)
{
    const int b = blockIdx.x, tid = threadIdx.x;
    const float* gb = gen + (size_t)b * Vd;
    const float* cb = cps + (size_t)b * CPSW;
    __shared__ float red[32];
    __shared__ float adds[VOOVd - Vd];

    float m = -3.0e38f;
    for (int i = tid; i < Vd;   i += 512) m = fmaxf(m, gb[i]);
    for (int i = tid; i < CPSW; i += 512) m = fmaxf(m, cb[i]);
    m = block_reduce_max(m, red);

    float s = 0.f;
    for (int i = tid; i < Vd;   i += 512) s += expf(gb[i] - m);
    for (int i = tid; i < CPSW; i += 512) s += expf(cb[i] - m);
    s = block_reduce_sum(s, red);
    float logS = logf(s);

    for (int i = tid; i < Vd; i += 512)
        out[(size_t)b*VOOVd + i] = logf(expf(gb[i] - m) + expf(cb[i] - m)) - logS;

    for (int i = tid; i < (VOOVd - Vd); i += 512) adds[i] = 0.f;
    __syncthreads();
    if (tid < TB) {
        int nk = nounk[b*TB + tid];
        if (nk >= Vd) atomicAdd(&adds[nk - Vd], expf(cb[Vd + tid] - m) / s);
    }
    __syncthreads();
    for (int i = tid; i < (VOOVd - Vd); i += 512) {
        float a = adds[i];
        out[(size_t)b*VOOVd + Vd + i] = (a > 0.f) ? logf(fmaxf(a, 1e-38f)) : NEGV;
    }
}

// =============================== host ======================================
extern "C" void kernel_launch(void* const* d_in, const int* in_sizes, int n_in,
                              void* d_out, int out_size)
{
    (void)in_sizes; (void)n_in; (void)out_size;
    const int*   dec_last_w = (const int*)  d_in[0];
    const float* dec_last_h = (const float*)d_in[1];
    const float* usdx_h     = (const float*)d_in[2];
    const float* bspn_h     = (const float*)d_in[3];
    const float* pvaspn_h   = (const float*)d_in[4];
    const float* db         = (const float*)d_in[5];
    const int*   usdx_ids   = (const int*)  d_in[6];
    const int*   bspn_ids   = (const int*)  d_in[7];
    const int*   pvaspn_ids = (const int*)  d_in[8];
    const int*   bspn_nounk = (const int*)  d_in[9];
    /* d_in[10] bspn_onehot unused */
    const float* emb_table  = (const float*)d_in[11];
    const float* attn_W     = (const float*)d_in[12];
    const float* attn_b     = (const float*)d_in[13];
    const float* v_w        = (const float*)d_in[14];
    const float* Wcopy_w    = (const float*)d_in[15];
    const float* Wcopy_b    = (const float*)d_in[16];
    const float* Wgen_w     = (const float*)d_in[17];
    const float* Wgen_b     = (const float*)d_in[18];
    const float* W_ih       = (const float*)d_in[19];
    const float* W_hh       = (const float*)d_in[20];
    const float* b_ih       = (const float*)d_in[21];
    const float* b_hh       = (const float*)d_in[22];
    float* out = (float*)d_out;

    float *pre1,*score,*gi,*gh,*hnew,*gen,*cpraw,*cps;
    __nv_bfloat16 *Xbf,*hnewbf,*Wa,*Wb,*Wc,*Whh,*Wih,*Wgn;
    cudaGetSymbolAddress((void**)&pre1,  g_pre1);
    cudaGetSymbolAddress((void**)&score, g_score);
    cudaGetSymbolAddress((void**)&Xbf,   g_Xbf);
    cudaGetSymbolAddress((void**)&gi,    g_gi);
    cudaGetSymbolAddress((void**)&gh,    g_gh);
    cudaGetSymbolAddress((void**)&hnew,  g_hnew);
    cudaGetSymbolAddress((void**)&hnewbf,g_hnewbf);
    cudaGetSymbolAddress((void**)&gen,   g_gen);
    cudaGetSymbolAddress((void**)&cpraw, g_cpraw);
    cudaGetSymbolAddress((void**)&cps,   g_cps);
    cudaGetSymbolAddress((void**)&Wa,    g_Wa);
    cudaGetSymbolAddress((void**)&Wb,    g_Wb);
    cudaGetSymbolAddress((void**)&Wc,    g_Wc);
    cudaGetSymbolAddress((void**)&Whh,   g_Whh);
    cudaGetSymbolAddress((void**)&Wih,   g_Wih);
    cudaGetSymbolAddress((void**)&Wgn,   g_Wgn);

    cudaMemsetAsync(cps, 0, sizeof(float)*(size_t)Bdim*CPSW);

    // weight conversions (f32 -> bf16, slice / pad)
    conv_k<<<512,256>>>(Wa,  attn_W,  Hd, Hd, 2*Hd, 0,  Hd);
    conv_k<<<512,256>>>(Wb,  attn_W,  Hd, Hd, 2*Hd, Hd, Hd);
    conv_k<<<512,256>>>(Wc,  Wcopy_w, Hd, Hd, Hd,   0,  Hd);
    conv_k<<<512,256>>>(Whh, W_hh,  G3H, Hd,  Hd,   0,  Hd);
    conv_k<<<2048,256>>>(Wih, W_ih, G3H, XR,  XR,   0,  XP);
    conv_k<<<2048,256>>>(Wgn, Wgen_w, Vd, Hd, Hd,   0,  Hd);

    // pre1 = h0 @ Wa^T + attn_b
    mma_gemm<0,0><<<dim3(1,4), 256>>>(dec_last_h, Hd, 8, Wa, Hd, Hd,
        attn_b, 0, nullptr, 0, 1, pre1, Hd);

    // attention scores (fused tanh(.+pre1)·v epilogue)
    mma_gemm<1,0><<<dim3(Bdim*TU/128,1), 256>>>(usdx_h, Hd, 8, Wb, Hd, Hd,
        pre1, 1, v_w, 0, TU, score, 0);
    mma_gemm<1,0><<<dim3(Bdim*TB/128,1), 256>>>(bspn_h, Hd, 8, Wb, Hd, Hd,
        pre1, 1, v_w, 0, TB, score + Bdim*TU, 0);
    mma_gemm<1,0><<<dim3(Bdim*TP/128,1), 256>>>(pvaspn_h, Hd, 8, Wb, Hd, Hd,
        pre1, 1, v_w, 0, TP, score + Bdim*(TU+TB), 0);

    softmax_ctx_k<<<Bdim, 256>>>(score,                usdx_ids,   usdx_h,   TU, Xbf, Hd);
    softmax_ctx_k<<<Bdim, 256>>>(score + Bdim*TU,      bspn_ids,   bspn_h,   TB, Xbf, Hd + Hd);
    softmax_ctx_k<<<Bdim, 256>>>(score + Bdim*(TU+TB), pvaspn_ids, pvaspn_h, TP, Xbf, Hd + 2*Hd);
    embdb_k<<<Bdim, 256>>>(dec_last_w, emb_table, db, Xbf);

    // GRU: gi = X @ W_ih^T + b_ih ; gh = h0 @ W_hh^T + b_hh
    mma_gemm<0,1><<<dim3(1,12), 256>>>(Xbf, XP, 33, Wih, XP, G3H,
        b_ih, 0, nullptr, 0, 1, gi, G3H);
    mma_gemm<0,0><<<dim3(1,12), 256>>>(dec_last_h, Hd, 8, Whh, Hd, G3H,
        b_hh, 0, nullptr, 0, 1, gh, G3H);
    gate_k<<<Bdim, Hd>>>(gi, gh, dec_last_h, hnew, hnewbf);

    // gen = hnew @ Wgen^T + b
    mma_gemm<0,1><<<dim3(1,24), 256>>>(hnewbf, Hd, 8, Wgn, Hd, Vd,
        Wgen_b, 0, nullptr, 0, 1, gen, Vd);

    // cp_raw = sum_h tanh(bspn_h@Wcopy^T + b) * hnew
    mma_gemm<1,0><<<dim3(Bdim*TB/128,1), 256>>>(bspn_h, Hd, 8, Wc, Hd, Hd,
        Wcopy_b, 0, hnew, 1, TB, cpraw, 0);

    scatter_k<<<Bdim, TB>>>(cpraw, bspn_ids, bspn_nounk, cps);
    final_k<<<Bdim, 512>>>(gen, cps, bspn_nounk, out);
}

// round 8
// speedup vs baseline: 5.2533x; 3.0143x over previous
#include <cuda_runtime.h>
#include <cuda_bf16.h>
#include <math.h>
#include <stdint.h>

#define Bdim   128
#define TU     256
#define TB     128
#define TP     64
#define Hd     512
#define Vd     3000
#define VOOVd  3400
#define PTRd   32
#define XP     2112      // padded X width (2080 -> 33*64)
#define XR     2080
#define G3H    1536
#define CPSW   3128
#define NEGV   (-1e20f)

// ---------------- scratch ----------------
__device__ float g_pre1 [Bdim*Hd];
__device__ float g_score[Bdim*(TU+TB+TP)];
__device__ __nv_bfloat16 g_Xbf[Bdim*XP];
__device__ float g_gi   [Bdim*G3H];
__device__ float g_gh   [Bdim*G3H];
__device__ float g_hnew [Bdim*Hd];
__device__ __nv_bfloat16 g_hnewbf[Bdim*Hd];
__device__ float g_gen  [Bdim*Vd];
__device__ float g_cpraw[Bdim*TB];
__device__ float g_cps  [Bdim*CPSW];
__device__ __nv_bfloat16 g_Wa [Hd*Hd];
__device__ __nv_bfloat16 g_Wb [Hd*Hd];
__device__ __nv_bfloat16 g_Wc [Hd*Hd];
__device__ __nv_bfloat16 g_Whh[G3H*Hd];
__device__ __nv_bfloat16 g_Wih[G3H*XP];
__device__ __nv_bfloat16 g_Wgn[Vd*Hd];
__device__ __nv_bfloat16 g_hbf  [Bdim*Hd];
__device__ __nv_bfloat16 g_ubf  [Bdim*TU*Hd];
__device__ __nv_bfloat16 g_bbf  [Bdim*TB*Hd];
__device__ __nv_bfloat16 g_pbf  [Bdim*TP*Hd];

// ---------------- helpers ----------------
__device__ __forceinline__ uint32_t smem_u32(const void* p) {
    uint32_t a;
    asm("{ .reg .u64 t; cvta.to.shared.u64 t, %1; cvt.u32.u64 %0, t; }" : "=r"(a) : "l"(p));
    return a;
}
__device__ __forceinline__ void ldmx4(uint32_t* r, uint32_t addr) {
    asm volatile("ldmatrix.sync.aligned.m8n8.x4.shared.b16 {%0,%1,%2,%3}, [%4];"
        : "=r"(r[0]), "=r"(r[1]), "=r"(r[2]), "=r"(r[3]) : "r"(addr));
}
__device__ __forceinline__ void mma16816(float* d, const uint32_t* a, const uint32_t* b) {
    asm volatile("mma.sync.aligned.m16n8k16.row.col.f32.bf16.bf16.f32 "
        "{%0,%1,%2,%3}, {%4,%5,%6,%7}, {%8,%9}, {%0,%1,%2,%3};"
        : "+f"(d[0]), "+f"(d[1]), "+f"(d[2]), "+f"(d[3])
        : "r"(a[0]), "r"(a[1]), "r"(a[2]), "r"(a[3]), "r"(b[0]), "r"(b[1]));
}
__device__ __forceinline__ void cpa16(uint32_t d, const void* s) {
    asm volatile("cp.async.cg.shared.global [%0], [%1], 16;" :: "r"(d), "l"(s));
}
__device__ __forceinline__ void cpa16z(uint32_t d, const void* s, int sz) {
    asm volatile("cp.async.cg.shared.global [%0], [%1], 16, %2;" :: "r"(d), "l"(s), "r"(sz));
}
#define CPCOMMIT() asm volatile("cp.async.commit_group;" ::: "memory")
#define SWZ(x) ((x) ^ (((x) >> 3) & 0x70))

__device__ __forceinline__ float tanh_f(float x) {
    float a = fabsf(x);
    if (a < 0.6f) {
        float t = x * x;
        return x * (1.f + t * (-0.33333334f + t * (0.13333333f +
                    t * (-0.05396825f + t * 0.02186949f))));
    }
    return tanhf(x);
}

// ==================== pipelined mma.sync bf16 GEMM ====================
// C = A[M x K] @ B[Nb x K]^T, fp32 acc, 128x128 CTA tile, K in 64 chunks,
// 2-stage cp.async double buffer.
// MODE 0: C[r, n] = acc + add[n]                       (grid.y tiles N by 128)
// MODE 1: atomicAdd(C[r], sum_n tanh(acc+add[bi,n])*mul[bi,n])  (grid.y = n-slice)
template<int MODE>
__global__ void __launch_bounds__(256, 2)
mma_gemm(const __nv_bfloat16* __restrict__ A, int lda, int KC /*K/64*/,
         const __nv_bfloat16* __restrict__ B, int ldb, int Nb,
         const float* __restrict__ addp, int add_per_b,
         const float* __restrict__ mulp, int mul_per_b,
         int Tdim, float* __restrict__ Co, int ldc)
{
    extern __shared__ __align__(128) char sm[];
    const uint32_t sb = smem_u32(sm);
    float* add_s  = (float*)(sm + 65536);
    float* mul_s  = add_s + 256;
    float* rowacc = add_s + 512;

    const int tid = threadIdx.x, wid = tid >> 5, lane = tid & 31;
    const int warpM = wid & 3, warpN = wid >> 2;
    const int row0 = blockIdx.x * 128;
    const int nb0  = blockIdx.y * 128;

    if (MODE == 0) {
        if (tid < 128) {
            int c = nb0 + tid;
            add_s[tid] = (c < Nb) ? addp[c] : 0.f;
        }
    } else {
        const int b0 = row0 / Tdim;
        if (tid < 256) {
            int bi = tid >> 7, nl = tid & 127;
            int b = b0 + bi; if (b > Bdim - 1) b = Bdim - 1;
            add_s[tid] = addp[add_per_b ? (b * Hd + nb0 + nl) : (nb0 + nl)];
            mul_s[tid] = mulp[mul_per_b ? (b * Hd + nb0 + nl) : (nb0 + nl)];
        }
        if (tid < 128) rowacc[tid] = 0.f;
    }

    // tile loader: A 128x64 bf16 + B 128x64 bf16, swizzled, via cp.async
    auto load_tiles = [&](int st, int k0) {
        const uint32_t sA = sb + st * 16384;
        const uint32_t sB = sb + 32768 + st * 16384;
#pragma unroll
        for (int i = 0; i < 4; i++) {
            int c = tid + (i << 8);
            int row = c >> 3, col = (c & 7) << 3;          // col in bf16 elems
            cpa16(sA + SWZ(row * 128 + col * 2),
                  A + (size_t)(row0 + row) * lda + k0 + col);
        }
#pragma unroll
        for (int i = 0; i < 4; i++) {
            int c = tid + (i << 8);
            int row = c >> 3, col = (c & 7) << 3;
            int n = nb0 + row;
            cpa16z(sB + SWZ(row * 128 + col * 2),
                   B + (size_t)n * ldb + k0 + col, (n < Nb) ? 16 : 0);
        }
    };

    float acc[2][8][4];
#pragma unroll
    for (int t = 0; t < 2; t++)
#pragma unroll
        for (int j = 0; j < 8; j++)
#pragma unroll
            for (int q = 0; q < 4; q++) acc[t][j][q] = 0.f;

    load_tiles(0, 0);
    CPCOMMIT();

    for (int kt = 0; kt < KC; kt++) {
        if (kt + 1 < KC) {
            load_tiles((kt + 1) & 1, (kt + 1) * 64);
            CPCOMMIT();
            asm volatile("cp.async.wait_group 1;" ::: "memory");
        } else {
            asm volatile("cp.async.wait_group 0;" ::: "memory");
        }
        __syncthreads();
        const uint32_t As_b = sb + (kt & 1) * 16384;
        const uint32_t Bs_b = sb + 32768 + (kt & 1) * 16384;
#pragma unroll
        for (int kc = 0; kc < 4; kc++) {
            uint32_t af[2][4];
#pragma unroll
            for (int t = 0; t < 2; t++) {
                int row  = warpM * 32 + t * 16 + (lane & 15);
                int bcol = kc * 32 + ((lane >> 4) << 4);
                ldmx4(af[t], As_b + SWZ(row * 128 + bcol));
            }
            uint32_t bfr[4][4];
#pragma unroll
            for (int g = 0; g < 4; g++) {
                int row  = warpN * 64 + g * 16 + (lane & 7) + ((lane >> 4) << 3);
                int bcol = kc * 32 + (((lane >> 3) & 1) << 4);
                ldmx4(bfr[g], Bs_b + SWZ(row * 128 + bcol));
            }
#pragma unroll
            for (int t = 0; t < 2; t++)
#pragma unroll
                for (int g = 0; g < 4; g++) {
                    mma16816(acc[t][2*g],   af[t], &bfr[g][0]);
                    mma16816(acc[t][2*g+1], af[t], &bfr[g][2]);
                }
        }
        __syncthreads();
    }

    if (MODE == 0) {
#pragma unroll
        for (int t = 0; t < 2; t++) {
            int r0 = row0 + warpM * 32 + t * 16 + (lane >> 2);
#pragma unroll
            for (int j = 0; j < 8; j++) {
                int c = nb0 + warpN * 64 + j * 8 + ((lane & 3) << 1);
                if (c < Nb) {
                    float b0v = add_s[c - nb0], b1v = add_s[c + 1 - nb0];
                    Co[(size_t)r0 * ldc + c]         = acc[t][j][0] + b0v;
                    Co[(size_t)r0 * ldc + c + 1]     = acc[t][j][1] + b1v;
                    Co[(size_t)(r0+8) * ldc + c]     = acc[t][j][2] + b0v;
                    Co[(size_t)(r0+8) * ldc + c + 1] = acc[t][j][3] + b1v;
                }
            }
        }
    } else {
        float rs[4] = {0.f, 0.f, 0.f, 0.f};
#pragma unroll
        for (int t = 0; t < 2; t++) {
            int bi = (warpM * 32 + t * 16) / Tdim;
            const float* aS = add_s + bi * 128;
            const float* mS = mul_s + bi * 128;
#pragma unroll
            for (int j = 0; j < 8; j++) {
                int n = warpN * 64 + j * 8 + ((lane & 3) << 1);
                rs[t*2+0] += tanh_f(acc[t][j][0] + aS[n])   * mS[n]
                           + tanh_f(acc[t][j][1] + aS[n+1]) * mS[n+1];
                rs[t*2+1] += tanh_f(acc[t][j][2] + aS[n])   * mS[n]
                           + tanh_f(acc[t][j][3] + aS[n+1]) * mS[n+1];
            }
        }
#pragma unroll
        for (int q = 0; q < 4; q++) {
            rs[q] += __shfl_xor_sync(0xffffffffu, rs[q], 1);
            rs[q] += __shfl_xor_sync(0xffffffffu, rs[q], 2);
        }
        if ((lane & 3) == 0) {
#pragma unroll
            for (int t = 0; t < 2; t++) {
                int rloc = warpM * 32 + t * 16 + (lane >> 2);
                atomicAdd(&rowacc[rloc],     rs[t*2+0]);
                atomicAdd(&rowacc[rloc + 8], rs[t*2+1]);
            }
        }
        __syncthreads();
        if (tid < 128) atomicAdd(&Co[row0 + tid], rowacc[tid]);
    }
}

// ---------------- fused f32->bf16 conversion (vectorized, 10 jobs) ----------
struct CJob { const float* src; __nv_bfloat16* dst; int rows, cols, lds, coff, ldd; };
struct CJobs { CJob j[10]; };

__global__ void __launch_bounds__(256)
conv_all(CJobs js)
{
    CJob J = js.j[blockIdx.y];
    const int w4 = J.ldd >> 2;
    const int nch = J.rows * w4;
    for (int i = blockIdx.x * 256 + threadIdx.x; i < nch; i += gridDim.x * 256) {
        int r = i / w4, c4 = (i - r * w4) << 2;
        uint2 o;
        if (c4 < J.cols) {
            float4 f = *(const float4*)(J.src + (size_t)r * J.lds + J.coff + c4);
            __nv_bfloat162 p0 = __floats2bfloat162_rn(f.x, f.y);
            __nv_bfloat162 p1 = __floats2bfloat162_rn(f.z, f.w);
            o.x = *(uint32_t*)&p0; o.y = *(uint32_t*)&p1;
        } else {
            o = make_uint2(0u, 0u);
        }
        *(uint2*)(J.dst + (size_t)r * J.ldd + c4) = o;
    }
}

// ---------------- reductions ----------------
__device__ __forceinline__ float block_reduce_max(float val, float* red) {
    int tid = threadIdx.x, nw = blockDim.x >> 5;
    for (int o = 16; o; o >>= 1) val = fmaxf(val, __shfl_down_sync(0xffffffffu, val, o));
    if ((tid & 31) == 0) red[tid >> 5] = val;
    __syncthreads();
    if (tid < 32) {
        val = (tid < nw) ? red[tid] : -3.0e38f;
        for (int o = 16; o; o >>= 1) val = fmaxf(val, __shfl_down_sync(0xffffffffu, val, o));
        if (tid == 0) red[0] = val;
    }
    __syncthreads();
    val = red[0]; __syncthreads();
    return val;
}
__device__ __forceinline__ float block_reduce_sum(float val, float* red) {
    int tid = threadIdx.x, nw = blockDim.x >> 5;
    for (int o = 16; o; o >>= 1) val += __shfl_down_sync(0xffffffffu, val, o);
    if ((tid & 31) == 0) red[tid >> 5] = val;
    __syncthreads();
    if (tid < 32) {
        val = (tid < nw) ? red[tid] : 0.f;
        for (int o = 16; o; o >>= 1) val += __shfl_down_sync(0xffffffffu, val, o);
        if (tid == 0) red[0] = val;
    }
    __syncthreads();
    val = red[0]; __syncthreads();
    return val;
}

// masked softmax + context (reads bf16 enc); grid (B, 2): y = half of H
__global__ void __launch_bounds__(256)
softmax_ctx_k(const float* __restrict__ score, const int* __restrict__ ids,
              const __nv_bfloat16* __restrict__ enc, int T,
              __nv_bfloat16* __restrict__ xout, int xofs)
{
    const int b = blockIdx.x, hb = blockIdx.y, tid = threadIdx.x;
    __shared__ float aw[TU];
    __shared__ float red[32];
    float sv = -3.0e38f;
    if (tid < T) {
        float s = score[b * T + tid];
        if (ids[b * T + tid] == 0) s = NEGV;
        aw[tid] = s; sv = s;
    }
    float m = block_reduce_max(sv, red);
    float e = 0.f;
    if (tid < T) { e = expf(aw[tid] - m); aw[tid] = e; }
    float ssum = block_reduce_sum(e, red);
    float inv = 1.f / ssum;
    const int h = hb * 256 + tid;
    float c0 = 0.f;
    const __nv_bfloat16* eb = enc + (size_t)b * T * Hd + h;
#pragma unroll 4
    for (int t = 0; t < T; t++)
        c0 = fmaf(aw[t] * inv, __bfloat162float(eb[t * Hd]), c0);
    xout[(size_t)b * XP + xofs + h] = __float2bfloat16(c0);
}

__global__ void embdb_k(const int* __restrict__ w, const float* __restrict__ emb,
                        const float* __restrict__ db, __nv_bfloat16* __restrict__ X)
{
    int b = blockIdx.x, tid = threadIdx.x;
    int widx = w[b];
    for (int i = tid; i < Hd; i += 256)
        X[(size_t)b * XP + i] = __float2bfloat16(emb[(size_t)widx * Hd + i]);
    if (tid < PTRd)
        X[(size_t)b * XP + 2048 + tid] = __float2bfloat16(db[b * PTRd + tid]);
    if (tid >= PTRd && tid < PTRd + (XP - XR))
        X[(size_t)b * XP + XR + (tid - PTRd)] = __float2bfloat16(0.f);
}

__global__ void gate_k(const float* __restrict__ gi, const float* __restrict__ gh,
                       const float* __restrict__ h0, float* __restrict__ hnew,
                       __nv_bfloat16* __restrict__ hnewbf)
{
    int b = blockIdx.x, h = threadIdx.x;
    float ir  = gi[b*G3H + h],        hr = gh[b*G3H + h];
    float iz  = gi[b*G3H + Hd + h],   hz = gh[b*G3H + Hd + h];
    float inn = gi[b*G3H + 2*Hd + h], hn = gh[b*G3H + 2*Hd + h];
    float rr = 1.f / (1.f + expf(-(ir + hr)));
    float z  = 1.f / (1.f + expf(-(iz + hz)));
    float n  = tanhf(inn + rr * hn);
    float v  = (1.f - z) * n + z * h0[b*Hd + h];
    hnew[b*Hd + h]   = v;
    hnewbf[b*Hd + h] = __float2bfloat16(v);
}

__global__ void scatter_k(const float* __restrict__ cpraw, const int* __restrict__ bids,
                          const int* __restrict__ nounk, float* __restrict__ cps)
{
    int b = blockIdx.x, t = threadIdx.x;
    float val = cpraw[b*TB + t];
    if (bids[b*TB + t] == 0) val = NEGV;
    int nk = nounk[b*TB + t];
    int col = (nk < Vd) ? nk : (Vd + t);
    atomicAdd(&cps[(size_t)b*CPSW + col], val);
}

__global__ void __launch_bounds__(512)
final_k(const float* __restrict__ gen, const float* __restrict__ cps,
        const int* __restrict__ nounk, float* __restrict__ out)
{
    const int b = blockIdx.x, tid = threadIdx.x;
    const float* gb = gen + (size_t)b * Vd;
    const float* cb = cps + (size_t)b * CPSW;
    __shared__ float red[32];
    __shared__ float adds[VOOVd - Vd];

    float m = -3.0e38f;
    for (int i = tid; i < Vd;   i += 512) m = fmaxf(m, gb[i]);
    for (int i = tid; i < CPSW; i += 512) m = fmaxf(m, cb[i]);
    m = block_reduce_max(m, red);

    float s = 0.f;
    for (int i = tid; i < Vd;   i += 512) s += expf(gb[i] - m);
    for (int i = tid; i < CPSW; i += 512) s += expf(cb[i] - m);
    s = block_reduce_sum(s, red);
    float logS = logf(s);

    for (int i = tid; i < Vd; i += 512)
        out[(size_t)b*VOOVd + i] = logf(expf(gb[i] - m) + expf(cb[i] - m)) - logS;

    for (int i = tid; i < (VOOVd - Vd); i += 512) adds[i] = 0.f;
    __syncthreads();
    if (tid < TB) {
        int nk = nounk[b*TB + tid];
        if (nk >= Vd) atomicAdd(&adds[nk - Vd], expf(cb[Vd + tid] - m) / s);
    }
    __syncthreads();
    for (int i = tid; i < (VOOVd - Vd); i += 512) {
        float a = adds[i];
        out[(size_t)b*VOOVd + Vd + i] = (a > 0.f) ? logf(fmaxf(a, 1e-38f)) : NEGV;
    }
}

// =============================== host ======================================
#define SMEMSZ 68096

extern "C" void kernel_launch(void* const* d_in, const int* in_sizes, int n_in,
                              void* d_out, int out_size)
{
    (void)in_sizes; (void)n_in; (void)out_size;
    const int*   dec_last_w = (const int*)  d_in[0];
    const float* dec_last_h = (const float*)d_in[1];
    const float* usdx_h     = (const float*)d_in[2];
    const float* bspn_h     = (const float*)d_in[3];
    const float* pvaspn_h   = (const float*)d_in[4];
    const float* db         = (const float*)d_in[5];
    const int*   usdx_ids   = (const int*)  d_in[6];
    const int*   bspn_ids   = (const int*)  d_in[7];
    const int*   pvaspn_ids = (const int*)  d_in[8];
    const int*   bspn_nounk = (const int*)  d_in[9];
    /* d_in[10] bspn_onehot unused */
    const float* emb_table  = (const float*)d_in[11];
    const float* attn_W     = (const float*)d_in[12];
    const float* attn_b     = (const float*)d_in[13];
    const float* v_w        = (const float*)d_in[14];
    const float* Wcopy_w    = (const float*)d_in[15];
    const float* Wcopy_b    = (const float*)d_in[16];
    const float* Wgen_w     = (const float*)d_in[17];
    const float* Wgen_b     = (const float*)d_in[18];
    const float* W_ih       = (const float*)d_in[19];
    const float* W_hh       = (const float*)d_in[20];
    const float* b_ih       = (const float*)d_in[21];
    const float* b_hh       = (const float*)d_in[22];
    float* out = (float*)d_out;

    float *pre1,*score,*gi,*gh,*hnew,*gen,*cpraw,*cps;
    __nv_bfloat16 *Xbf,*hnewbf,*Wa,*Wb,*Wc,*Whh,*Wih,*Wgn,*hbf,*ubf,*bbf,*pbf;
    cudaGetSymbolAddress((void**)&pre1,  g_pre1);
    cudaGetSymbolAddress((void**)&score, g_score);
    cudaGetSymbolAddress((void**)&Xbf,   g_Xbf);
    cudaGetSymbolAddress((void**)&gi,    g_gi);
    cudaGetSymbolAddress((void**)&gh,    g_gh);
    cudaGetSymbolAddress((void**)&hnew,  g_hnew);
    cudaGetSymbolAddress((void**)&hnewbf,g_hnewbf);
    cudaGetSymbolAddress((void**)&gen,   g_gen);
    cudaGetSymbolAddress((void**)&cpraw, g_cpraw);
    cudaGetSymbolAddress((void**)&cps,   g_cps);
    cudaGetSymbolAddress((void**)&Wa,    g_Wa);
    cudaGetSymbolAddress((void**)&Wb,    g_Wb);
    cudaGetSymbolAddress((void**)&Wc,    g_Wc);
    cudaGetSymbolAddress((void**)&Whh,   g_Whh);
    cudaGetSymbolAddress((void**)&Wih,   g_Wih);
    cudaGetSymbolAddress((void**)&Wgn,   g_Wgn);
    cudaGetSymbolAddress((void**)&hbf,   g_hbf);
    cudaGetSymbolAddress((void**)&ubf,   g_ubf);
    cudaGetSymbolAddress((void**)&bbf,   g_bbf);
    cudaGetSymbolAddress((void**)&pbf,   g_pbf);

    cudaFuncSetAttribute(mma_gemm<0>, cudaFuncAttributeMaxDynamicSharedMemorySize, SMEMSZ);
    cudaFuncSetAttribute(mma_gemm<1>, cudaFuncAttributeMaxDynamicSharedMemorySize, SMEMSZ);

    // launches 1-3: zero the atomic targets
    cudaMemsetAsync(score, 0, sizeof(float)*Bdim*(TU+TB+TP));
    cudaMemsetAsync(cpraw, 0, sizeof(float)*Bdim*TB);
    cudaMemsetAsync(cps,   0, sizeof(float)*(size_t)Bdim*CPSW);

    // launch 4: all f32->bf16 conversions
    CJobs js;
    js.j[0] = { attn_W,     Wa,  Hd,        Hd, 2*Hd, 0,  Hd };
    js.j[1] = { attn_W,     Wb,  Hd,        Hd, 2*Hd, Hd, Hd };
    js.j[2] = { Wcopy_w,    Wc,  Hd,        Hd, Hd,   0,  Hd };
    js.j[3] = { W_hh,       Whh, G3H,       Hd, Hd,   0,  Hd };
    js.j[4] = { W_ih,       Wih, G3H,       XR, XR,   0,  XP };
    js.j[5] = { Wgen_w,     Wgn, Vd,        Hd, Hd,   0,  Hd };
    js.j[6] = { dec_last_h, hbf, Bdim,      Hd, Hd,   0,  Hd };
    js.j[7] = { usdx_h,     ubf, Bdim*TU,   Hd, Hd,   0,  Hd };
    js.j[8] = { bspn_h,     bbf, Bdim*TB,   Hd, Hd,   0,  Hd };
    js.j[9] = { pvaspn_h,   pbf, Bdim*TP,   Hd, Hd,   0,  Hd };
    conv_all<<<dim3(512, 10), 256>>>(js);

    // launch 5: pre1 = h0 @ Wa^T + attn_b
    mma_gemm<0><<<dim3(1,4), 256, SMEMSZ>>>(hbf, Hd, 8, Wa, Hd, Hd,
        attn_b, 0, nullptr, 0, 1, pre1, Hd);

    // launch 6 (ncu-captured): usdx attention score
    mma_gemm<1><<<dim3(Bdim*TU/128,4), 256, SMEMSZ>>>(ubf, Hd, 8, Wb, Hd, Hd,
        pre1, 1, v_w, 0, TU, score, 0);
    mma_gemm<1><<<dim3(Bdim*TB/128,4), 256, SMEMSZ>>>(bbf, Hd, 8, Wb, Hd, Hd,
        pre1, 1, v_w, 0, TB, score + Bdim*TU, 0);
    mma_gemm<1><<<dim3(Bdim*TP/128,4), 256, SMEMSZ>>>(pbf, Hd, 8, Wb, Hd, Hd,
        pre1, 1, v_w, 0, TP, score + Bdim*(TU+TB), 0);

    softmax_ctx_k<<<dim3(Bdim,2), 256>>>(score,                usdx_ids,   ubf, TU, Xbf, Hd);
    softmax_ctx_k<<<dim3(Bdim,2), 256>>>(score + Bdim*TU,      bspn_ids,   bbf, TB, Xbf, 2*Hd);
    softmax_ctx_k<<<dim3(Bdim,2), 256>>>(score + Bdim*(TU+TB), pvaspn_ids, pbf, TP, Xbf, 3*Hd);
    embdb_k<<<Bdim, 256>>>(dec_last_w, emb_table, db, Xbf);

    // GRU
    mma_gemm<0><<<dim3(1,12), 256, SMEMSZ>>>(Xbf, XP, 33, Wih, XP, G3H,
        b_ih, 0, nullptr, 0, 1, gi, G3H);
    mma_gemm<0><<<dim3(1,12), 256, SMEMSZ>>>(hbf, Hd, 8, Whh, Hd, G3H,
        b_hh, 0, nullptr, 0, 1, gh, G3H);
    gate_k<<<Bdim, Hd>>>(gi, gh, dec_last_h, hnew, hnewbf);

    // gen = hnew @ Wgen^T + b
    mma_gemm<0><<<dim3(1,24), 256, SMEMSZ>>>(hnewbf, Hd, 8, Wgn, Hd, Vd,
        Wgen_b, 0, nullptr, 0, 1, gen, Vd);

    // cp_raw = sum_h tanh(bspn_h@Wcopy^T + b) * hnew
    mma_gemm<1><<<dim3(Bdim*TB/128,4), 256, SMEMSZ>>>(bbf, Hd, 8, Wc, Hd, Hd,
        Wcopy_b, 0, hnew, 1, TB, cpraw, 0);

    scatter_k<<<Bdim, TB>>>(cpraw, bspn_ids, bspn_nounk, cps);
    final_k<<<Bdim, 512>>>(gen, cps, bspn_nounk, out);
}

// round 9
// speedup vs baseline: 5.8184x; 1.1076x over previous
#include <cuda_runtime.h>
#include <cuda_bf16.h>
#include <math.h>
#include <stdint.h>

#define Bdim   128
#define TU     256
#define TB     128
#define TP     64
#define Hd     512
#define Vd     3000
#define VOOVd  3400
#define PTRd   32
#define XP2    2176      // padded X width (2080 -> 17*128)
#define XR     2080
#define G3H    1536
#define CPSW   3128
#define NEGV   (-1e20f)
#define SC8    (1.f/256.f)   // fp8 operands are stored x16 each

// ---------------- scratch ----------------
__device__ float g_pre1 [Bdim*Hd];
__device__ float g_score[Bdim*(TU+TB+TP)];
__device__ float g_gi   [Bdim*G3H];
__device__ float g_gh   [Bdim*G3H];
__device__ float g_hnew [Bdim*Hd];
__device__ float g_gen  [Bdim*Vd];
__device__ float g_cpraw[Bdim*TB];
__device__ float g_cps  [Bdim*CPSW];
__device__ uint8_t g_W8a [Hd*Hd];
__device__ uint8_t g_W8b [Hd*Hd];
__device__ uint8_t g_W8c [Hd*Hd];
__device__ uint8_t g_W8hh[G3H*Hd];
__device__ uint8_t g_W8ih[G3H*XP2];
__device__ uint8_t g_W8gn[Vd*Hd];
__device__ uint8_t g_h8  [Bdim*Hd];
__device__ uint8_t g_u8  [Bdim*TU*Hd];
__device__ uint8_t g_b8  [Bdim*TB*Hd];
__device__ uint8_t g_p8  [Bdim*TP*Hd];
__device__ uint8_t g_X8  [Bdim*XP2];
__device__ uint8_t g_hn8 [Bdim*Hd];

// ---------------- helpers ----------------
__device__ __forceinline__ uint32_t smem_u32(const void* p) {
    uint32_t a;
    asm("{ .reg .u64 t; cvta.to.shared.u64 t, %1; cvt.u32.u64 %0, t; }" : "=r"(a) : "l"(p));
    return a;
}
__device__ __forceinline__ void ldmx4(uint32_t* r, uint32_t addr) {
    asm volatile("ldmatrix.sync.aligned.m8n8.x4.shared.b16 {%0,%1,%2,%3}, [%4];"
        : "=r"(r[0]), "=r"(r[1]), "=r"(r[2]), "=r"(r[3]) : "r"(addr));
}
__device__ __forceinline__ void mma8(float* d, const uint32_t* a, const uint32_t* b) {
    asm volatile("mma.sync.aligned.m16n8k32.row.col.f32.e4m3.e4m3.f32 "
        "{%0,%1,%2,%3}, {%4,%5,%6,%7}, {%8,%9}, {%0,%1,%2,%3};"
        : "+f"(d[0]), "+f"(d[1]), "+f"(d[2]), "+f"(d[3])
        : "r"(a[0]), "r"(a[1]), "r"(a[2]), "r"(a[3]), "r"(b[0]), "r"(b[1]));
}
__device__ __forceinline__ void cpa16(uint32_t d, const void* s) {
    asm volatile("cp.async.cg.shared.global [%0], [%1], 16;" :: "r"(d), "l"(s));
}
__device__ __forceinline__ void cpa16z(uint32_t d, const void* s, int sz) {
    asm volatile("cp.async.cg.shared.global [%0], [%1], 16, %2;" :: "r"(d), "l"(s), "r"(sz));
}
#define CPCOMMIT() asm volatile("cp.async.commit_group;" ::: "memory")
#define SWZ(x) ((x) ^ (((x) >> 3) & 0x70))

// 2 f32 -> packed e4m3x2 (x.y -> upper byte, x.x -> lower byte)
__device__ __forceinline__ uint16_t cvt2_e4m3(float lo, float hi) {
    uint16_t v;
    asm("cvt.rn.satfinite.e4m3x2.f32 %0, %1, %2;" : "=h"(v) : "f"(hi), "f"(lo));
    return v;
}
// packed e4m3x2 -> 2 f32
__device__ __forceinline__ float2 cvt_e4m3_2f(uint16_t v) {
    uint32_t h2;
    asm("cvt.rn.f16x2.e4m3x2 %0, %1;" : "=r"(h2) : "h"(v));
    __half2 h = *(__half2*)&h2;
    return make_float2(__half2float(h.x), __half2float(h.y));
}

__device__ __forceinline__ float tanh_f(float x) {
    float a = fabsf(x);
    if (a < 0.6f) {
        float t = x * x;
        return x * (1.f + t * (-0.33333334f + t * (0.13333333f +
                    t * (-0.05396825f + t * 0.02186949f))));
    }
    return tanhf(x);
}

// ==================== fp8 mma.sync GEMM ====================
// C = A[M x K] @ B[Nb x K]^T, e4m3 (x16 each) -> acc * 1/256.
// 128x128 CTA tile, K in 128-elem chunks (128B rows, SW128), 2-stage cp.async.
// MODE 0: C[r, n] = acc*SC8 + add[n]        (grid.x = 1, grid.y tiles N by 128)
// MODE 1: atomicAdd(C[r], sum_n tanh(acc*SC8 + add[bi,n]) * mul[bi,n]); grid.y = n-slice
// NS = 3: MODE1 3-span dispatch over blockIdx.x (usdx/bspn/pvaspn)
template<int MODE, int NS>
__global__ void __launch_bounds__(256, 2)
gemm8(const uint8_t* __restrict__ A0, const uint8_t* __restrict__ A1,
      const uint8_t* __restrict__ A2,
      int lda, int KC /*K/128*/,
      const uint8_t* __restrict__ B, int ldb, int Nb,
      const float* __restrict__ addp, int add_per_b,
      const float* __restrict__ mulp, int mul_per_b,
      int Td0, float* __restrict__ C0, float* __restrict__ C1,
      float* __restrict__ C2, int ldc)
{
    extern __shared__ __align__(128) char sm[];
    const uint32_t sb = smem_u32(sm);
    float* add_s  = (float*)(sm + 65536);
    float* mul_s  = add_s + 256;
    float* rowacc = add_s + 512;

    const int tid = threadIdx.x, wid = tid >> 5, lane = tid & 31;
    const int warpM = wid & 3, warpN = wid >> 2;
    const int nb0 = blockIdx.y * 128;

    const uint8_t* A;
    float* Co;
    int row0, Tdim;
    if (NS == 3) {
        int bx = blockIdx.x;
        if (bx < 256)      { A = A0; Co = C0; row0 = bx * 128;         Tdim = TU; }
        else if (bx < 384) { A = A1; Co = C1; row0 = (bx - 256) * 128; Tdim = TB; }
        else               { A = A2; Co = C2; row0 = (bx - 384) * 128; Tdim = TP; }
    } else {
        A = A0; Co = C0; row0 = blockIdx.x * 128; Tdim = Td0;
    }

    if (MODE == 0) {
        if (tid < 128) {
            int c = nb0 + tid;
            add_s[tid] = (c < Nb) ? addp[c] : 0.f;
        }
    } else {
        const int b0 = row0 / Tdim;
        {
            int bi = tid >> 7, nl = tid & 127;
            int b = b0 + bi; if (b > Bdim - 1) b = Bdim - 1;
            add_s[tid] = addp[add_per_b ? (b * Hd + nb0 + nl) : (nb0 + nl)];
            mul_s[tid] = mulp[mul_per_b ? (b * Hd + nb0 + nl) : (nb0 + nl)];
        }
        if (tid < 128) rowacc[tid] = 0.f;
    }

    // stage = A 128x128B + B 128x128B (16KB each)
    auto load_tiles = [&](int st, int k0) {
        const uint32_t sA = sb + st * 16384;
        const uint32_t sB = sb + 32768 + st * 16384;
#pragma unroll
        for (int i = 0; i < 4; i++) {
            int c = tid + (i << 8);
            int row = c >> 3, col = (c & 7) << 4;      // col in bytes (fp8 elems)
            cpa16(sA + SWZ(row * 128 + col),
                  A + (size_t)(row0 + row) * lda + k0 + col);
        }
#pragma unroll
        for (int i = 0; i < 4; i++) {
            int c = tid + (i << 8);
            int row = c >> 3, col = (c & 7) << 4;
            int n = nb0 + row;
            cpa16z(sB + SWZ(row * 128 + col),
                   B + (size_t)n * ldb + k0 + col, (n < Nb) ? 16 : 0);
        }
    };

    float acc[2][8][4];
#pragma unroll
    for (int t = 0; t < 2; t++)
#pragma unroll
        for (int j = 0; j < 8; j++)
#pragma unroll
            for (int q = 0; q < 4; q++) acc[t][j][q] = 0.f;

    load_tiles(0, 0);
    CPCOMMIT();

    for (int kt = 0; kt < KC; kt++) {
        if (kt + 1 < KC) {
            load_tiles((kt + 1) & 1, (kt + 1) * 128);
            CPCOMMIT();
            asm volatile("cp.async.wait_group 1;" ::: "memory");
        } else {
            asm volatile("cp.async.wait_group 0;" ::: "memory");
        }
        __syncthreads();
        const uint32_t As_b = sb + (kt & 1) * 16384;
        const uint32_t Bs_b = sb + 32768 + (kt & 1) * 16384;
#pragma unroll
        for (int kc = 0; kc < 4; kc++) {          // 4 x k32 per 128-elem chunk
            uint32_t af[2][4];
#pragma unroll
            for (int t = 0; t < 2; t++) {
                int row  = warpM * 32 + t * 16 + (lane & 15);
                int bcol = kc * 32 + ((lane >> 4) << 4);
                ldmx4(af[t], As_b + SWZ(row * 128 + bcol));
            }
            uint32_t bfr[4][4];
#pragma unroll
            for (int g = 0; g < 4; g++) {
                int row  = warpN * 64 + g * 16 + (lane & 7) + ((lane >> 4) << 3);
                int bcol = kc * 32 + (((lane >> 3) & 1) << 4);
                ldmx4(bfr[g], Bs_b + SWZ(row * 128 + bcol));
            }
#pragma unroll
            for (int t = 0; t < 2; t++)
#pragma unroll
                for (int g = 0; g < 4; g++) {
                    mma8(acc[t][2*g],   af[t], &bfr[g][0]);
                    mma8(acc[t][2*g+1], af[t], &bfr[g][2]);
                }
        }
        __syncthreads();
    }

    if (MODE == 0) {
#pragma unroll
        for (int t = 0; t < 2; t++) {
            int r0 = row0 + warpM * 32 + t * 16 + (lane >> 2);
#pragma unroll
            for (int j = 0; j < 8; j++) {
                int c = nb0 + warpN * 64 + j * 8 + ((lane & 3) << 1);
                if (c < Nb) {
                    float b0v = add_s[c - nb0], b1v = add_s[c + 1 - nb0];
                    Co[(size_t)r0 * ldc + c]         = acc[t][j][0] * SC8 + b0v;
                    Co[(size_t)r0 * ldc + c + 1]     = acc[t][j][1] * SC8 + b1v;
                    Co[(size_t)(r0+8) * ldc + c]     = acc[t][j][2] * SC8 + b0v;
                    Co[(size_t)(r0+8) * ldc + c + 1] = acc[t][j][3] * SC8 + b1v;
                }
            }
        }
    } else {
        float rs[4] = {0.f, 0.f, 0.f, 0.f};
#pragma unroll
        for (int t = 0; t < 2; t++) {
            int bi = (warpM * 32 + t * 16) / Tdim;
            const float* aS = add_s + bi * 128;
            const float* mS = mul_s + bi * 128;
#pragma unroll
            for (int j = 0; j < 8; j++) {
                int n = warpN * 64 + j * 8 + ((lane & 3) << 1);
                rs[t*2+0] += tanh_f(acc[t][j][0] * SC8 + aS[n])   * mS[n]
                           + tanh_f(acc[t][j][1] * SC8 + aS[n+1]) * mS[n+1];
                rs[t*2+1] += tanh_f(acc[t][j][2] * SC8 + aS[n])   * mS[n]
                           + tanh_f(acc[t][j][3] * SC8 + aS[n+1]) * mS[n+1];
            }
        }
#pragma unroll
        for (int q = 0; q < 4; q++) {
            rs[q] += __shfl_xor_sync(0xffffffffu, rs[q], 1);
            rs[q] += __shfl_xor_sync(0xffffffffu, rs[q], 2);
        }
        if ((lane & 3) == 0) {
#pragma unroll
            for (int t = 0; t < 2; t++) {
                int rloc = warpM * 32 + t * 16 + (lane >> 2);
                atomicAdd(&rowacc[rloc],     rs[t*2+0]);
                atomicAdd(&rowacc[rloc + 8], rs[t*2+1]);
            }
        }
        __syncthreads();
        if (tid < 128) atomicAdd(&Co[row0 + tid], rowacc[tid]);
    }
}

// ---------------- fused f32 -> e4m3(x16) conversion, 10 jobs ----------------
struct CJob { const float* src; uint8_t* dst; int rows, cols, lds, coff, ldd; };
struct CJobs { CJob j[10]; };

__global__ void __launch_bounds__(256)
conv_all(CJobs js)
{
    CJob J = js.j[blockIdx.y];
    const int w8 = J.ldd >> 3;
    const int nch = J.rows * w8;
    for (int i = blockIdx.x * 256 + threadIdx.x; i < nch; i += gridDim.x * 256) {
        int r = i / w8, c8 = (i - r * w8) << 3;
        uint32_t o0 = 0, o1 = 0;
        if (c8 < J.cols) {
            const float* s = J.src + (size_t)r * J.lds + J.coff + c8;
            float4 f0 = *(const float4*)s;
            float4 f1 = *(const float4*)(s + 4);
            o0 = (uint32_t)cvt2_e4m3(f0.x*16.f, f0.y*16.f)
               | ((uint32_t)cvt2_e4m3(f0.z*16.f, f0.w*16.f) << 16);
            o1 = (uint32_t)cvt2_e4m3(f1.x*16.f, f1.y*16.f)
               | ((uint32_t)cvt2_e4m3(f1.z*16.f, f1.w*16.f) << 16);
        }
        *(uint2*)(J.dst + (size_t)r * J.ldd + c8) = make_uint2(o0, o1);
    }
}

// ---------------- reductions ----------------
__device__ __forceinline__ float block_reduce_max(float val, float* red) {
    int tid = threadIdx.x, nw = blockDim.x >> 5;
    for (int o = 16; o; o >>= 1) val = fmaxf(val, __shfl_down_sync(0xffffffffu, val, o));
    if ((tid & 31) == 0) red[tid >> 5] = val;
    __syncthreads();
    if (tid < 32) {
        val = (tid < nw) ? red[tid] : -3.0e38f;
        for (int o = 16; o; o >>= 1) val = fmaxf(val, __shfl_down_sync(0xffffffffu, val, o));
        if (tid == 0) red[0] = val;
    }
    __syncthreads();
    val = red[0]; __syncthreads();
    return val;
}
__device__ __forceinline__ float block_reduce_sum(float val, float* red) {
    int tid = threadIdx.x, nw = blockDim.x >> 5;
    for (int o = 16; o; o >>= 1) val += __shfl_down_sync(0xffffffffu, val, o);
    if ((tid & 31) == 0) red[tid >> 5] = val;
    __syncthreads();
    if (tid < 32) {
        val = (tid < nw) ? red[tid] : 0.f;
        for (int o = 16; o; o >>= 1) val += __shfl_down_sync(0xffffffffu, val, o);
        if (tid == 0) red[0] = val;
    }
    __syncthreads();
    val = red[0]; __syncthreads();
    return val;
}

// masked softmax + context for all 3 spans (grid = (Bdim, 1, 3)); enc is fp8 x16.
// ctx written into X8 directly (already in the x16 domain).
__global__ void __launch_bounds__(256)
softmax3_k(const float* __restrict__ score,
           const int* __restrict__ ids_u, const int* __restrict__ ids_b,
           const int* __restrict__ ids_p,
           const uint8_t* __restrict__ e_u, const uint8_t* __restrict__ e_b,
           const uint8_t* __restrict__ e_p,
           uint8_t* __restrict__ X8)
{
    const int b = blockIdx.x, z = blockIdx.z, tid = threadIdx.x;
    int T; const int* ids; const uint8_t* enc; const float* sc;
    if (z == 0)      { T = TU; ids = ids_u; enc = e_u; sc = score; }
    else if (z == 1) { T = TB; ids = ids_b; enc = e_b; sc = score + Bdim*TU; }
    else             { T = TP; ids = ids_p; enc = e_p; sc = score + Bdim*(TU+TB); }

    __shared__ float aw[TU];
    __shared__ float red[32];
    float sv = -3.0e38f;
    if (tid < T) {
        float s = sc[b * T + tid];
        if (ids[b * T + tid] == 0) s = NEGV;
        aw[tid] = s; sv = s;
    }
    float m = block_reduce_max(sv, red);
    float e = 0.f;
    if (tid < T) { e = expf(aw[tid] - m); aw[tid] = e; }
    float ssum = block_reduce_sum(e, red);
    float inv = 1.f / ssum;

    const int h2 = tid << 1;                   // pair of H columns
    float c0 = 0.f, c1 = 0.f;
    const uint8_t* eb = enc + (size_t)b * T * Hd + h2;
#pragma unroll 4
    for (int t = 0; t < T; t++) {
        uint16_t v = *(const uint16_t*)(eb + (size_t)t * Hd);
        float2 f = cvt_e4m3_2f(v);
        float w = aw[t] * inv;
        c0 = fmaf(w, f.x, c0);
        c1 = fmaf(w, f.y, c1);
    }
    *(uint16_t*)(X8 + (size_t)b * XP2 + Hd * (z + 1) + h2) = cvt2_e4m3(c0, c1);
}

// embedding gather + db + pad into X8 (x16 domain)
__global__ void embdb_k(const int* __restrict__ w, const float* __restrict__ emb,
                        const float* __restrict__ db, uint8_t* __restrict__ X8)
{
    int b = blockIdx.x, tid = threadIdx.x;
    int widx = w[b];
    {   // emb: 512 elems = 256 pairs
        const float* e = emb + (size_t)widx * Hd + (tid << 1);
        *(uint16_t*)(X8 + (size_t)b * XP2 + (tid << 1)) =
            cvt2_e4m3(e[0] * 16.f, e[1] * 16.f);
    }
    if (tid < PTRd / 2) {
        const float* d = db + b * PTRd + (tid << 1);
        *(uint16_t*)(X8 + (size_t)b * XP2 + 2048 + (tid << 1)) =
            cvt2_e4m3(d[0] * 16.f, d[1] * 16.f);
    }
    if (tid < (XP2 - XR) / 2)
        *(uint16_t*)(X8 + (size_t)b * XP2 + XR + (tid << 1)) = 0;
}

__global__ void gate_k(const float* __restrict__ gi, const float* __restrict__ gh,
                       const float* __restrict__ h0, float* __restrict__ hnew,
                       uint8_t* __restrict__ hn8)
{
    int b = blockIdx.x, h = threadIdx.x;
    float ir  = gi[b*G3H + h],        hr = gh[b*G3H + h];
    float iz  = gi[b*G3H + Hd + h],   hz = gh[b*G3H + Hd + h];
    float inn = gi[b*G3H + 2*Hd + h], hn = gh[b*G3H + 2*Hd + h];
    float rr = 1.f / (1.f + expf(-(ir + hr)));
    float z  = 1.f / (1.f + expf(-(iz + hz)));
    float n  = tanhf(inn + rr * hn);
    float v  = (1.f - z) * n + z * h0[b*Hd + h];
    hnew[b*Hd + h] = v;
    uint16_t p = cvt2_e4m3(v * 16.f, 0.f);
    hn8[b*Hd + h] = (uint8_t)(p & 0xff);
}

__global__ void scatter_k(const float* __restrict__ cpraw, const int* __restrict__ bids,
                          const int* __restrict__ nounk, float* __restrict__ cps)
{
    int b = blockIdx.x, t = threadIdx.x;
    float val = cpraw[b*TB + t];
    if (bids[b*TB + t] == 0) val = NEGV;
    int nk = nounk[b*TB + t];
    int col = (nk < Vd) ? nk : (Vd + t);
    atomicAdd(&cps[(size_t)b*CPSW + col], val);
}

__global__ void __launch_bounds__(512)
final_k(const float* __restrict__ gen, const float* __restrict__ cps,
        const int* __restrict__ nounk, float* __restrict__ out)
{
    const int b = blockIdx.x, tid = threadIdx.x;
    const float* gb = gen + (size_t)b * Vd;
    const float* cb = cps + (size_t)b * CPSW;
    __shared__ float red[32];
    __shared__ float adds[VOOVd - Vd];

    float m = -3.0e38f;
    for (int i = tid; i < Vd;   i += 512) m = fmaxf(m, gb[i]);
    for (int i = tid; i < CPSW; i += 512) m = fmaxf(m, cb[i]);
    m = block_reduce_max(m, red);

    float s = 0.f;
    for (int i = tid; i < Vd;   i += 512) s += expf(gb[i] - m);
    for (int i = tid; i < CPSW; i += 512) s += expf(cb[i] - m);
    s = block_reduce_sum(s, red);
    float logS = logf(s);

    for (int i = tid; i < Vd; i += 512)
        out[(size_t)b*VOOVd + i] = logf(expf(gb[i] - m) + expf(cb[i] - m)) - logS;

    for (int i = tid; i < (VOOVd - Vd); i += 512) adds[i] = 0.f;
    __syncthreads();
    if (tid < TB) {
        int nk = nounk[b*TB + tid];
        if (nk >= Vd) atomicAdd(&adds[nk - Vd], expf(cb[Vd + tid] - m) / s);
    }
    __syncthreads();
    for (int i = tid; i < (VOOVd - Vd); i += 512) {
        float a = adds[i];
        out[(size_t)b*VOOVd + Vd + i] = (a > 0.f) ? logf(fmaxf(a, 1e-38f)) : NEGV;
    }
}

// =============================== host ======================================
#define SMEMSZ 68096

extern "C" void kernel_launch(void* const* d_in, const int* in_sizes, int n_in,
                              void* d_out, int out_size)
{
    (void)in_sizes; (void)n_in; (void)out_size;
    const int*   dec_last_w = (const int*)  d_in[0];
    const float* dec_last_h = (const float*)d_in[1];
    const float* usdx_h     = (const float*)d_in[2];
    const float* bspn_h     = (const float*)d_in[3];
    const float* pvaspn_h   = (const float*)d_in[4];
    const float* db         = (const float*)d_in[5];
    const int*   usdx_ids   = (const int*)  d_in[6];
    const int*   bspn_ids   = (const int*)  d_in[7];
    const int*   pvaspn_ids = (const int*)  d_in[8];
    const int*   bspn_nounk = (const int*)  d_in[9];
    /* d_in[10] bspn_onehot unused */
    const float* emb_table  = (const float*)d_in[11];
    const float* attn_W     = (const float*)d_in[12];
    const float* attn_b     = (const float*)d_in[13];
    const float* v_w        = (const float*)d_in[14];
    const float* Wcopy_w    = (const float*)d_in[15];
    const float* Wcopy_b    = (const float*)d_in[16];
    const float* Wgen_w     = (const float*)d_in[17];
    const float* Wgen_b     = (const float*)d_in[18];
    const float* W_ih       = (const float*)d_in[19];
    const float* W_hh       = (const float*)d_in[20];
    const float* b_ih       = (const float*)d_in[21];
    const float* b_hh       = (const float*)d_in[22];
    float* out = (float*)d_out;

    float *pre1,*score,*gi,*gh,*hnew,*gen,*cpraw,*cps;
    uint8_t *W8a,*W8b,*W8c,*W8hh,*W8ih,*W8gn,*h8,*u8,*b8,*p8,*X8,*hn8;
    cudaGetSymbolAddress((void**)&pre1,  g_pre1);
    cudaGetSymbolAddress((void**)&score, g_score);
    cudaGetSymbolAddress((void**)&gi,    g_gi);
    cudaGetSymbolAddress((void**)&gh,    g_gh);
    cudaGetSymbolAddress((void**)&hnew,  g_hnew);
    cudaGetSymbolAddress((void**)&gen,   g_gen);
    cudaGetSymbolAddress((void**)&cpraw, g_cpraw);
    cudaGetSymbolAddress((void**)&cps,   g_cps);
    cudaGetSymbolAddress((void**)&W8a,   g_W8a);
    cudaGetSymbolAddress((void**)&W8b,   g_W8b);
    cudaGetSymbolAddress((void**)&W8c,   g_W8c);
    cudaGetSymbolAddress((void**)&W8hh,  g_W8hh);
    cudaGetSymbolAddress((void**)&W8ih,  g_W8ih);
    cudaGetSymbolAddress((void**)&W8gn,  g_W8gn);
    cudaGetSymbolAddress((void**)&h8,    g_h8);
    cudaGetSymbolAddress((void**)&u8,    g_u8);
    cudaGetSymbolAddress((void**)&b8,    g_b8);
    cudaGetSymbolAddress((void**)&p8,    g_p8);
    cudaGetSymbolAddress((void**)&X8,    g_X8);
    cudaGetSymbolAddress((void**)&hn8,   g_hn8);

    cudaFuncSetAttribute(gemm8<0,1>, cudaFuncAttributeMaxDynamicSharedMemorySize, SMEMSZ);
    cudaFuncSetAttribute(gemm8<1,1>, cudaFuncAttributeMaxDynamicSharedMemorySize, SMEMSZ);
    cudaFuncSetAttribute(gemm8<1,3>, cudaFuncAttributeMaxDynamicSharedMemorySize, SMEMSZ);

    // 1-3: zero atomic targets
    cudaMemsetAsync(score, 0, sizeof(float)*Bdim*(TU+TB+TP));
    cudaMemsetAsync(cpraw, 0, sizeof(float)*Bdim*TB);
    cudaMemsetAsync(cps,   0, sizeof(float)*(size_t)Bdim*CPSW);

    // 4: all f32 -> fp8(x16) conversions
    CJobs js;
    js.j[0] = { attn_W,     W8a,  Hd,      Hd, 2*Hd, 0,  Hd  };
    js.j[1] = { attn_W,     W8b,  Hd,      Hd, 2*Hd, Hd, Hd  };
    js.j[2] = { Wcopy_w,    W8c,  Hd,      Hd, Hd,   0,  Hd  };
    js.j[3] = { W_hh,       W8hh, G3H,     Hd, Hd,   0,  Hd  };
    js.j[4] = { W_ih,       W8ih, G3H,     XR, XR,   0,  XP2 };
    js.j[5] = { Wgen_w,     W8gn, Vd,      Hd, Hd,   0,  Hd  };
    js.j[6] = { dec_last_h, h8,   Bdim,    Hd, Hd,   0,  Hd  };
    js.j[7] = { usdx_h,     u8,   Bdim*TU, Hd, Hd,   0,  Hd  };
    js.j[8] = { bspn_h,     b8,   Bdim*TB, Hd, Hd,   0,  Hd  };
    js.j[9] = { pvaspn_h,   p8,   Bdim*TP, Hd, Hd,   0,  Hd  };
    conv_all<<<dim3(1024, 10), 256>>>(js);

    // 5: pre1 = h0 @ Wa^T + attn_b
    gemm8<0,1><<<dim3(1,4), 256, SMEMSZ>>>(h8, nullptr, nullptr, Hd, 4,
        W8a, Hd, Hd, attn_b, 0, nullptr, 0, 1, pre1, nullptr, nullptr, Hd);

    // 6 (ncu-captured): ALL attention scores, one launch
    gemm8<1,3><<<dim3(448,4), 256, SMEMSZ>>>(u8, b8, p8, Hd, 4,
        W8b, Hd, Hd, pre1, 1, v_w, 0, 0,
        score, score + Bdim*TU, score + Bdim*(TU+TB), 0);

    // 7: all three masked softmax + ctx
    softmax3_k<<<dim3(Bdim,1,3), 256>>>(score, usdx_ids, bspn_ids, pvaspn_ids,
                                        u8, b8, p8, X8);
    // 8: emb + db + pad
    embdb_k<<<Bdim, 256>>>(dec_last_w, emb_table, db, X8);

    // 9-10: GRU GEMMs
    gemm8<0,1><<<dim3(1,12), 256, SMEMSZ>>>(X8, nullptr, nullptr, XP2, 17,
        W8ih, XP2, G3H, b_ih, 0, nullptr, 0, 1, gi, nullptr, nullptr, G3H);
    gemm8<0,1><<<dim3(1,12), 256, SMEMSZ>>>(h8, nullptr, nullptr, Hd, 4,
        W8hh, Hd, G3H, b_hh, 0, nullptr, 0, 1, gh, nullptr, nullptr, G3H);
    // 11: gate
    gate_k<<<Bdim, Hd>>>(gi, gh, dec_last_h, hnew, hn8);

    // 12: gen = hnew @ Wgen^T + b
    gemm8<0,1><<<dim3(1,24), 256, SMEMSZ>>>(hn8, nullptr, nullptr, Hd, 4,
        W8gn, Hd, Vd, Wgen_b, 0, nullptr, 0, 1, gen, nullptr, nullptr, Vd);

    // 13: cp_raw = sum_h tanh(bspn_h@Wcopy^T + b) * hnew
    gemm8<1,1><<<dim3(Bdim*TB/128,4), 256, SMEMSZ>>>(b8, nullptr, nullptr, Hd, 4,
        W8c, Hd, Hd, Wcopy_b, 0, hnew, 1, TB, cpraw, nullptr, nullptr, 0);

    // 14-15: scatter + final
    scatter_k<<<Bdim, TB>>>(cpraw, bspn_ids, bspn_nounk, cps);
    final_k<<<Bdim, 512>>>(gen, cps, bspn_nounk, out);
}